// round 16
// baseline (speedup 1.0000x reference)
#include <cuda_runtime.h>
#include <math.h>

#define BB   64
#define NN   4096
#define DD   1024
#define DIN  2048
#define DHID 4096
#define NOUT 1000

typedef unsigned long long ull;

// ---- scratch (device globals; no allocation allowed) ----
__device__ float g_xn[BB * DD];        // normalized encoder
__device__ float g_z[BB * NN];         // sparsemax input scores
__device__ float g_memvec[BB * DD];    // weighted memory readout (plain stores)
__device__ float g_h1[BB * DHID];      // hidden pre-activations (bias + atomic acc)
__device__ float g_sink;               // DCE-blocker for the L2 warm kernel

// ---------------------------------------------------------------------------
// PRE-NORM (main, critical path): xn = enc / max(||enc||,1e-6). 64 blocks.
// ---------------------------------------------------------------------------
__global__ void pre_norm(const float* __restrict__ enc) {
    int b = blockIdx.x;
    __shared__ float red[256];
    float ssq = 0.f;
    for (int i = threadIdx.x; i < DD; i += 256) {
        float v = enc[b * DD + i];
        ssq = fmaf(v, v, ssq);
    }
    red[threadIdx.x] = ssq;
    __syncthreads();
    for (int s = 128; s > 0; s >>= 1) {
        if (threadIdx.x < s) red[threadIdx.x] += red[threadIdx.x + s];
        __syncthreads();
    }
    float inv = 1.f / fmaxf(sqrtf(red[0]), 1e-6f);
    for (int i = threadIdx.x; i < DD; i += 256)
        g_xn[b * DD + i] = enc[b * DD + i] * inv;
}

// ---------------------------------------------------------------------------
// PRE-INIT (side stream): h1 = b1 (bcast), out = b2 (bcast). 1274 blocks.
// ---------------------------------------------------------------------------
__global__ void pre_init(const float* __restrict__ b1,
                         const float* __restrict__ b2,
                         float* __restrict__ out) {
    int bid = blockIdx.x;
    if (bid < 1024) {
        int i = bid * 256 + threadIdx.x;               // BB*DHID
        g_h1[i] = b1[i & (DHID - 1)];
    } else {
        int i = (bid - 1024) * 256 + threadIdx.x;      // BB*NOUT
        if (i < BB * NOUT) out[i] = b2[i % NOUT];
    }
}

// ---------------------------------------------------------------------------
// K1: the 1.07 GB pass (AT DRAM ROOFLINE, 6.65 TB/s — do not touch).
// ---------------------------------------------------------------------------
__global__ void __launch_bounds__(256) k1_scores(const float* __restrict__ mem) {
    int warp = threadIdx.x >> 5, lane = threadIdx.x & 31;
    int rbase = blockIdx.x * 64 + warp * 8;
    int b = rbase >> 12;

    const float4* x4 = (const float4*)g_xn + (size_t)b * (DD / 4);
    float4 x[8];
#pragma unroll
    for (int i = 0; i < 8; i++) x[i] = x4[lane + i * 32];

    const float4* mrow = (const float4*)mem + (size_t)rbase * (DD / 4);

#pragma unroll
    for (int rr = 0; rr < 8; rr += 2) {
        const float4* A = mrow + rr * (DD / 4);
        const float4* C = A + (DD / 4);
        float4 a[8], c[8];
#pragma unroll
        for (int i = 0; i < 8; i++) {
            a[i] = __ldcs(&A[lane + i * 32]);
            c[i] = __ldcs(&C[lane + i * 32]);
        }
        float d0 = 0.f, s0 = 0.f, d1 = 0.f, s1 = 0.f;
#pragma unroll
        for (int i = 0; i < 8; i++) {
            float4 xv = x[i];
            d0 = fmaf(a[i].x, xv.x, fmaf(a[i].y, xv.y, fmaf(a[i].z, xv.z, fmaf(a[i].w, xv.w, d0))));
            s0 = fmaf(a[i].x, a[i].x, fmaf(a[i].y, a[i].y, fmaf(a[i].z, a[i].z, fmaf(a[i].w, a[i].w, s0))));
            d1 = fmaf(c[i].x, xv.x, fmaf(c[i].y, xv.y, fmaf(c[i].z, xv.z, fmaf(c[i].w, xv.w, d1))));
            s1 = fmaf(c[i].x, c[i].x, fmaf(c[i].y, c[i].y, fmaf(c[i].z, c[i].z, fmaf(c[i].w, c[i].w, s1))));
        }
#pragma unroll
        for (int o = 16; o; o >>= 1) {
            d0 += __shfl_xor_sync(0xFFFFFFFFu, d0, o);
            s0 += __shfl_xor_sync(0xFFFFFFFFu, s0, o);
            d1 += __shfl_xor_sync(0xFFFFFFFFu, d1, o);
            s1 += __shfl_xor_sync(0xFFFFFFFFu, s1, o);
        }
        if (lane == 0) {
            g_z[rbase + rr]     = d0 / fmaxf(sqrtf(s0), 1e-6f) - 1.0f;
            g_z[rbase + rr + 1] = d1 / fmaxf(sqrtf(s1), 1e-6f) - 1.0f;
        }
    }
}

// ---------------------------------------------------------------------------
// K2G: sparsemax (Michelot, 1 barrier/iter) FUSED with the sparse gather.
//      Block b: compute support in smem, then memvec[b,:] = sum w*mem[b,idx,:]
//      with 8-row unroll (MLP=8) and PLAIN stores (sole writer — no atomics,
//      no memvec zero-init needed). 64 blocks x 512 threads.
// ---------------------------------------------------------------------------
__global__ void __launch_bounds__(512) k2g_sparsemax_gather(const float* __restrict__ mem) {
    int b = blockIdx.x, t = threadIdx.x;
    int lane = t & 31, w = t >> 5;             // 16 warps
    __shared__ float sS[2][16], sK[2][16];
    __shared__ int cnt;
    __shared__ int   s_idx[NN];                // worst-case support
    __shared__ float s_w[NN];

    float loc[8];
#pragma unroll
    for (int i = 0; i < 8; i++) loc[i] = g_z[b * NN + t + i * 512];

    // initial tau = (sum - 1)/N
    float S = 0.f;
#pragma unroll
    for (int i = 0; i < 8; i++) S += loc[i];
#pragma unroll
    for (int o = 16; o; o >>= 1) S += __shfl_xor_sync(0xFFFFFFFFu, S, o);
    if (lane == 0) sS[0][w] = S;
    __syncthreads();
    float tau;
    {
        float ss = 0.f;
#pragma unroll
        for (int i = 0; i < 16; i++) ss += sS[0][i];
        tau = (ss - 1.f) / (float)NN;
    }

    int par = 1;
    for (int it = 0; it < 48; it++) {
        float s = 0.f, k = 0.f;
#pragma unroll
        for (int i = 0; i < 8; i++) {
            float v = loc[i];
            if (v > tau) { s += v; k += 1.f; }
        }
#pragma unroll
        for (int o = 16; o; o >>= 1) {
            s += __shfl_xor_sync(0xFFFFFFFFu, s, o);
            k += __shfl_xor_sync(0xFFFFFFFFu, k, o);
        }
        if (lane == 0) { sS[par][w] = s; sK[par][w] = k; }
        __syncthreads();
        float ss = 0.f, kk = 0.f;
#pragma unroll
        for (int i = 0; i < 16; i++) { ss += sS[par][i]; kk += sK[par][i]; }
        float tn = (ss - 1.f) / kk;            // identical in all threads
        if (!(tn > tau)) break;                // uniform decision
        tau = tn;
        par ^= 1;
    }

    // compact support into SMEM
    if (t == 0) cnt = 0;
    __syncthreads();
#pragma unroll
    for (int i = 0; i < 8; i++) {
        float wv = loc[i] - tau;
        if (wv > 0.f) {
            int p = atomicAdd(&cnt, 1);
            s_idx[p] = t + i * 512;
            s_w[p] = wv;
        }
    }
    __syncthreads();
    int nnz = cnt;

    // gather: thread t owns float2 column [2t, 2t+1]; 8-row unroll (MLP=8)
    const float2* base = (const float2*)(mem + (size_t)b * NN * DD);
    float2 acc = make_float2(0.f, 0.f);
    int i = 0;
    for (; i + 8 <= nnz; i += 8) {
        float2 m[8];
        float  wv[8];
#pragma unroll
        for (int j = 0; j < 8; j++) {
            int idx = s_idx[i + j];            // broadcast LDS
            wv[j] = s_w[i + j];
            m[j] = __ldcs(&base[(size_t)idx * (DD / 2) + t]);
        }
#pragma unroll
        for (int j = 0; j < 8; j++) {
            acc.x = fmaf(wv[j], m[j].x, acc.x);
            acc.y = fmaf(wv[j], m[j].y, acc.y);
        }
    }
    for (; i < nnz; i++) {
        int idx = s_idx[i];
        float wv = s_w[i];
        float2 m = __ldcs(&base[(size_t)idx * (DD / 2) + t]);
        acc.x = fmaf(wv, m.x, acc.x);
        acc.y = fmaf(wv, m.y, acc.y);
    }
    ((float2*)g_memvec)[b * (DD / 2) + t] = acc;   // plain store: sole writer
}

// ---------------------------------------------------------------------------
// K4a (SIDE STREAM, concurrent with k1/k2g):
//     h1 += enc @ W1[:, 0:1024]^T   — depends only on pre_init (h1=b1).
// ---------------------------------------------------------------------------
__global__ void k4a_fc1(const float* __restrict__ enc,
                        const float* __restrict__ W1) {
    __shared__ float2 sw2[64][33];
    __shared__ float2 sh2[32][33];
    int t = threadIdx.x;
    int obase = blockIdx.x * 64;
    int koff = blockIdx.y * 512;
    int ol = t & 31;
    int bg = t >> 5;

    ull accA[4] = {0ull, 0ull, 0ull, 0ull};
    ull accB[4] = {0ull, 0ull, 0ull, 0ull};

    for (int kc = koff; kc < koff + 512; kc += 32) {
#pragma unroll
        for (int i = 0; i < 8; i++) {
            int e = t + i * 256;
            int row = e >> 5, col = e & 31;
            ((float*)&sh2[row >> 1][col])[row & 1] = enc[row * DD + kc + col];
        }
#pragma unroll
        for (int i = 0; i < 8; i++) {
            int e = t + i * 256;
            int row = e >> 5, col = e & 31;
            float wv = W1[(size_t)(obase + row) * DIN + kc + col];
            sw2[row][col] = make_float2(wv, wv);
        }
        __syncthreads();
#pragma unroll
        for (int kk = 0; kk < 32; kk++) {
            ull wa = *(const ull*)&sw2[ol][kk];
            ull wb = *(const ull*)&sw2[ol + 32][kk];
#pragma unroll
            for (int j = 0; j < 4; j++) {
                ull h2 = *(const ull*)&sh2[bg * 4 + j][kk];
                asm("fma.rn.f32x2 %0, %1, %2, %0;" : "+l"(accA[j]) : "l"(h2), "l"(wa));
                asm("fma.rn.f32x2 %0, %1, %2, %0;" : "+l"(accB[j]) : "l"(h2), "l"(wb));
            }
        }
        __syncthreads();
    }
    int o0 = obase + ol, o1 = obase + 32 + ol;
#pragma unroll
    for (int j = 0; j < 4; j++) {
        float lo, hi;
        int p = bg * 8 + j * 2;
        asm("mov.b64 {%0, %1}, %2;" : "=f"(lo), "=f"(hi) : "l"(accA[j]));
        atomicAdd(&g_h1[(size_t)p * DHID + o0], lo);
        atomicAdd(&g_h1[(size_t)(p + 1) * DHID + o0], hi);
        asm("mov.b64 {%0, %1}, %2;" : "=f"(lo), "=f"(hi) : "l"(accB[j]));
        atomicAdd(&g_h1[(size_t)p * DHID + o1], lo);
        atomicAdd(&g_h1[(size_t)(p + 1) * DHID + o1], hi);
    }
}

// ---------------------------------------------------------------------------
// WARM (SIDE STREAM, after k4a, still under k1): touch W1[:,1024:2048] and W2
//     via __ldcg so k4b/k5 hit L2 instead of DRAM.
// ---------------------------------------------------------------------------
__global__ void l2_warm(const float* __restrict__ W1,
                        const float* __restrict__ W2) {
    int t = threadIdx.x;
    float acc = 0.f;
    if (blockIdx.x < 2048) {
        int row = blockIdx.x * 2;
#pragma unroll
        for (int r = 0; r < 2; r++) {
            const float4* p = (const float4*)(W1 + (size_t)(row + r) * DIN + DD);
            float4 v = __ldcg(&p[t]);
            acc += v.x + v.y + v.z + v.w;
        }
    } else {
        int row = blockIdx.x - 2048;
        const float4* p = (const float4*)(W2 + (size_t)row * DHID);
#pragma unroll
        for (int r = 0; r < 4; r++) {
            float4 v = __ldcg(&p[t + r * 256]);
            acc += v.x + v.y + v.z + v.w;
        }
    }
    if (acc == 1.23456789e+30f) g_sink = acc;
}

// ---------------------------------------------------------------------------
// K4b half: h1 += memvec @ W1[:, 1024:2048]^T for OUTPUT columns
//     [xoff*64, (xoff+32)*64). grid (32, 2); K-chunk 512.
// ---------------------------------------------------------------------------
__global__ void k4b_fc1(const float* __restrict__ W1, int xoff) {
    __shared__ float2 sw2[64][33];
    __shared__ float2 sh2[32][33];
    int t = threadIdx.x;
    int obase = (blockIdx.x + xoff) * 64;
    int koff = blockIdx.y * 512;
    int ol = t & 31;
    int bg = t >> 5;

    ull accA[4] = {0ull, 0ull, 0ull, 0ull};
    ull accB[4] = {0ull, 0ull, 0ull, 0ull};

    for (int kc = koff; kc < koff + 512; kc += 32) {
#pragma unroll
        for (int i = 0; i < 8; i++) {
            int e = t + i * 256;
            int row = e >> 5, col = e & 31;
            ((float*)&sh2[row >> 1][col])[row & 1] = g_memvec[row * DD + kc + col];
        }
#pragma unroll
        for (int i = 0; i < 8; i++) {
            int e = t + i * 256;
            int row = e >> 5, col = e & 31;
            float wv = W1[(size_t)(obase + row) * DIN + DD + kc + col];
            sw2[row][col] = make_float2(wv, wv);
        }
        __syncthreads();
#pragma unroll
        for (int kk = 0; kk < 32; kk++) {
            ull wa = *(const ull*)&sw2[ol][kk];
            ull wb = *(const ull*)&sw2[ol + 32][kk];
#pragma unroll
            for (int j = 0; j < 4; j++) {
                ull h2 = *(const ull*)&sh2[bg * 4 + j][kk];
                asm("fma.rn.f32x2 %0, %1, %2, %0;" : "+l"(accA[j]) : "l"(h2), "l"(wa));
                asm("fma.rn.f32x2 %0, %1, %2, %0;" : "+l"(accB[j]) : "l"(h2), "l"(wb));
            }
        }
        __syncthreads();
    }
    int o0 = obase + ol, o1 = obase + 32 + ol;
#pragma unroll
    for (int j = 0; j < 4; j++) {
        float lo, hi;
        int p = bg * 8 + j * 2;
        asm("mov.b64 {%0, %1}, %2;" : "=f"(lo), "=f"(hi) : "l"(accA[j]));
        atomicAdd(&g_h1[(size_t)p * DHID + o0], lo);
        atomicAdd(&g_h1[(size_t)(p + 1) * DHID + o0], hi);
        asm("mov.b64 {%0, %1}, %2;" : "=f"(lo), "=f"(hi) : "l"(accB[j]));
        atomicAdd(&g_h1[(size_t)p * DHID + o1], lo);
        atomicAdd(&g_h1[(size_t)(p + 1) * DHID + o1], hi);
    }
}

// ---------------------------------------------------------------------------
// K5 half: out += relu(h1[:, K-range]) @ W2[:, K-range]^T for
//     K-range [yoff*512, (yoff+4)*512). grid (16, 4); relu fused.
// ---------------------------------------------------------------------------
__global__ void k5_fc2(const float* __restrict__ W2, float* __restrict__ out,
                       int yoff) {
    __shared__ float2 sw2[64][33];
    __shared__ float2 sh2[32][33];
    int t = threadIdx.x;
    int obase = blockIdx.x * 64;
    int kbeg = (blockIdx.y + yoff) * 512;
    int ol = t & 31;
    int bg = t >> 5;

    ull accA[4] = {0ull, 0ull, 0ull, 0ull};
    ull accB[4] = {0ull, 0ull, 0ull, 0ull};

    for (int kc = kbeg; kc < kbeg + 512; kc += 32) {
#pragma unroll
        for (int i = 0; i < 8; i++) {
            int e = t + i * 256;
            int row = e >> 5, col = e & 31;
            float v = fmaxf(g_h1[(size_t)row * DHID + kc + col], 0.f);  // relu
            ((float*)&sh2[row >> 1][col])[row & 1] = v;
        }
#pragma unroll
        for (int i = 0; i < 8; i++) {
            int e = t + i * 256;
            int row = e >> 5, col = e & 31;
            int o = obase + row;
            float wv = (o < NOUT) ? W2[(size_t)o * DHID + kc + col] : 0.f;
            sw2[row][col] = make_float2(wv, wv);
        }
        __syncthreads();
#pragma unroll
        for (int kk = 0; kk < 32; kk++) {
            ull wa = *(const ull*)&sw2[ol][kk];
            ull wb = *(const ull*)&sw2[ol + 32][kk];
#pragma unroll
            for (int j = 0; j < 4; j++) {
                ull h2 = *(const ull*)&sh2[bg * 4 + j][kk];
                asm("fma.rn.f32x2 %0, %1, %2, %0;" : "+l"(accA[j]) : "l"(h2), "l"(wa));
                asm("fma.rn.f32x2 %0, %1, %2, %0;" : "+l"(accB[j]) : "l"(h2), "l"(wb));
            }
        }
        __syncthreads();
    }
    int o0 = obase + ol, o1 = obase + 32 + ol;
#pragma unroll
    for (int j = 0; j < 4; j++) {
        float lo, hi;
        int p = bg * 8 + j * 2;
        if (o0 < NOUT) {
            asm("mov.b64 {%0, %1}, %2;" : "=f"(lo), "=f"(hi) : "l"(accA[j]));
            atomicAdd(&out[(size_t)p * NOUT + o0], lo);
            atomicAdd(&out[(size_t)(p + 1) * NOUT + o0], hi);
        }
        if (o1 < NOUT) {
            asm("mov.b64 {%0, %1}, %2;" : "=f"(lo), "=f"(hi) : "l"(accB[j]));
            atomicAdd(&out[(size_t)p * NOUT + o1], lo);
            atomicAdd(&out[(size_t)(p + 1) * NOUT + o1], hi);
        }
    }
}

// ---------------------------------------------------------------------------
// Lazy stream/events (the guard-validated 2-stream topology): created on the
// FIRST (non-captured) call; capture only records record/wait.
// ---------------------------------------------------------------------------
static cudaStream_t side_stream() {
    static cudaStream_t s = [] {
        cudaStream_t t;
        cudaStreamCreateWithFlags(&t, cudaStreamNonBlocking);
        return t;
    }();
    return s;
}
static cudaEvent_t lazy_event(int i) {
    static cudaEvent_t e[4] = {};
    if (!e[i]) cudaEventCreateWithFlags(&e[i], cudaEventDisableTiming);
    return e[i];
}

// ---------------------------------------------------------------------------
extern "C" void kernel_launch(void* const* d_in, const int* in_sizes, int n_in,
                              void* d_out, int out_size) {
    const float* enc = (const float*)d_in[0];   // [64,1024]
    const float* mem = (const float*)d_in[1];   // [64,4096,1024]
    const float* W1  = (const float*)d_in[2];   // [4096,2048]
    const float* b1  = (const float*)d_in[3];   // [4096]
    const float* W2  = (const float*)d_in[4];   // [1000,4096]
    const float* b2  = (const float*)d_in[5];   // [1000]
    float* out = (float*)d_out;                 // [64,1000]

    cudaStream_t s2 = side_stream();
    cudaEvent_t evF  = lazy_event(0);           // fork at capture start
    cudaEvent_t evK2 = lazy_event(1);           // k2g done (main)
    cudaEvent_t evJ  = lazy_event(2);           // k4a done (side)
    cudaEvent_t evB  = lazy_event(3);           // side branch done

    // fork: side stream does inits + k4a + warm under k1's window
    cudaEventRecord(evF, 0);
    cudaStreamWaitEvent(s2, evF, 0);
    pre_init<<<1274, 256, 0, s2>>>(b1, b2, out);
    k4a_fc1<<<dim3(BB, 2), 256, 0, s2>>>(enc, W1);
    cudaEventRecord(evJ, s2);                   // k4a (h1 enc-half) complete
    l2_warm<<<3048, 256, 0, s2>>>(W1, W2);

    // main stream: critical path
    pre_norm<<<BB, 256>>>(enc);
    k1_scores<<<(BB * NN) / 64, 256>>>(mem);
    k2g_sparsemax_gather<<<BB, 512>>>(mem);     // sparsemax + gather fused
    cudaEventRecord(evK2, 0);

    // pipelined k4b->k5 halves over 2048-wide h1-column ranges:
    //   half B on the side stream (past k4a/warm; wait k2g for memvec)
    cudaStreamWaitEvent(s2, evK2, 0);
    k4b_fc1<<<dim3(32, 2), 256, 0, s2>>>(W1, 32);    // h1 cols [2048,4096)
    k5_fc2<<<dim3(16, 4), 256, 0, s2>>>(W2, out, 4); // K [2048,4096)
    cudaEventRecord(evB, s2);

    //   half A on the main stream (needs k4a done: k5-A reads its columns;
    //   evJ also transitively covers pre_init for out=b2)
    cudaStreamWaitEvent(0, evJ, 0);
    k4b_fc1<<<dim3(32, 2), 256>>>(W1, 0);            // h1 cols [0,2048)
    k5_fc2<<<dim3(16, 4), 256>>>(W2, out, 0);        // K [0,2048)

    // join side branch back into the captured (main) stream
    cudaStreamWaitEvent(0, evB, 0);
}